// round 10
// baseline (speedup 1.0000x reference)
#include <cuda_runtime.h>
#include <cuda_bf16.h>
#include <math.h>

// ---------------- problem constants ----------------
#define NE_    100000
#define NR_    200
#define RDIM_  384
#define BB     8192
#define NCOL   406          // 6 scalar cols + 2*NR
#define GAMMA_F 12.0f
#define NS     40           // n's per (row,side) on the MUFU pipe; rest via bf16 smem table (even!)
#define NSLICE 4            // d sliced into 4 groups of 32
#define RB     38           // row-blocks per slice: 4*38 = 152 blocks = 1 wave on GB300
#define ROWS_PER_BLK 216    // ceil(8192/38)

// ---------------- scratch (__device__ globals; no allocs allowed) ----------------
__device__ float    g_Wc[512 * 256];            // folded e_p_emb weight (512 KB)
__device__ float    g_P[2 * BB * 256];          // e_p: s rows [0,B), o rows [B,2B) (16 MB)
__device__ float    g_scabs[BB];                // per-row sc_abs
__device__ float2   g_TW[2 * BB * 200];         // per (row-side, n): (t as float, w) (26 MB)
__device__ unsigned g_Tb[NSLICE * 1000 * 32];   // bf16x2 pos-emb table, [slice][t][lane] (512 KB)
__device__ float    g_prel[NSLICE * BB];        // per-slice partial sc_rel sums

#define LOGK (13.287712379549449f / 128.0f)     // log2(10000)/128

// ======================================================================
// Kernel 0a: fold w_e (512x128) into single real GEMM weight Wc (512x256)
// ======================================================================
__global__ void k_wc(const float* __restrict__ w_e) {
    int k = blockIdx.x;        // 0..511
    int j = threadIdx.x;       // 0..255
    float v;
    if (j < 128) {
        v = w_e[k * 128 + j];
        if (k >= 256) v = -v;
    } else {
        v = w_e[(k ^ 256) * 128 + (j - 128)];
        if (k < 256) v = -v;
    }
    g_Wc[k * 256 + j] = v;
}

// ======================================================================
// Kernel 0b: build bf16 pos-emb table: g_Tb[slice][t*32 + lane] = (cos, sin)
// slice = d>>5, lane = d&31.  Conflict-free layout for warp=row, lane=d reads.
// ======================================================================
__global__ void k_tbuild() {
    int t = blockIdx.x;        // 0..999
    int d = threadIdx.x;       // 0..127
    float f = exp2f(-(float)d * LOGK);
    float s, c;
    sincosf((float)t * f, &s, &c);   // full-precision build (one-time)
    __nv_bfloat162 h2 = __floats2bfloat162_rn(c, s);
    g_Tb[(size_t)(d >> 5) * 32000 + t * 32 + (d & 31)] =
        *reinterpret_cast<unsigned*>(&h2);
}

// ======================================================================
// Kernel 1: per row — t_emb + sc_abs, and prestage (t, w) pairs into g_TW
// ======================================================================
__global__ void __launch_bounds__(256) k_gather(
    const int* __restrict__ x, int xs,
    const float* __restrict__ e_emb,
    const float* __restrict__ r_emb,
    const float* __restrict__ d_frq, const float* __restrict__ d_phi,
    const float* __restrict__ d_amp,
    const float* __restrict__ m_frq, const float* __restrict__ m_phi,
    const float* __restrict__ m_amp,
    const float* __restrict__ w_rp)
{
    __shared__ float st[256];
    __shared__ float ot[256];
    __shared__ float red8[8];

    const int b   = blockIdx.x;
    const int tid = threadIdx.x;
    const int base = b * NCOL;

    const int s_idx = x[(base + 0) * xs];
    const int r_idx = x[(base + 1) * xs];
    const int o_idx = x[(base + 2) * xs];
    const float dv  = (float)x[(base + 3) * xs];
    const float mv  = (float)x[(base + 4) * xs];

    // stage (t, w) into g_TW: cols 6..205 = c_s, 206..405 = c_o
    for (int i = tid; i < 400; i += 256) {
        int side = i / 200;
        int n    = i - side * 200;
        int t    = x[(base + 6 + i) * xs];
        float w  = w_rp[r_idx * 200 + n];
        g_TW[(size_t)(side ? (BB + b) : b) * 200 + n] = make_float2((float)t, w);
    }

    // t_emb (j = tid covers all 256 dims)
    {
        const int j  = tid;
        const int jm = (j < 128) ? j : (j - 128);
        {
            const size_t e = (size_t)s_idx;
            float angd = fmaf(dv, d_frq[e * 256 + j], d_phi[e * 256 + j]);
            float angm = fmaf(mv, m_frq[e * 256 + j], m_phi[e * 256 + j]);
            float ad = d_amp[e * 128 + jm];
            float am = m_amp[e * 128 + jm];
            st[j] = (j < 128) ? (ad * __cosf(angd) + am * __cosf(angm))
                              : (ad * __sinf(angd) + am * __sinf(angm));
        }
        {
            const size_t e = (size_t)o_idx;
            float angd = fmaf(dv, d_frq[e * 256 + j], d_phi[e * 256 + j]);
            float angm = fmaf(mv, m_frq[e * 256 + j], m_phi[e * 256 + j]);
            float ad = d_amp[e * 128 + jm];
            float am = m_amp[e * 128 + jm];
            ot[j] = (j < 128) ? (ad * __cosf(angd) + am * __cosf(angm))
                              : (ad * __sinf(angd) + am * __sinf(angm));
        }
    }
    __syncthreads();

    // sc_abs over k = 0..383
    const float scale = (float)(3.141592653589793 / sqrt(6.0 / (double)(NR_ + RDIM_)));
    const size_t sb = (size_t)s_idx * 512;
    const size_t ob = (size_t)o_idx * 512;
    float sum = 0.0f;
    for (int k = tid; k < 384; k += 256) {
        float pr = r_emb[(size_t)r_idx * 384 + k] * scale;
        float sn, cs;
        __sincosf(pr, &sn, &cs);
        float re_s, im_s, re_o, im_o;
        if (k < 256) {
            re_s = e_emb[sb + k];
            im_s = e_emb[sb + 256 + k];
            re_o = e_emb[ob + k];
            im_o = e_emb[ob + 256 + k];
        } else {
            re_s = st[k - 256];  im_s = st[k - 128];
            re_o = ot[k - 256];  im_o = ot[k - 128];
        }
        float re = re_s * cs - im_s * sn - re_o;
        float im = re_s * sn + im_s * cs - im_o;
        sum += sqrtf(re * re + im * im);
    }

    #pragma unroll
    for (int off = 16; off; off >>= 1) sum += __shfl_down_sync(0xffffffffu, sum, off);
    if ((tid & 31) == 0) red8[tid >> 5] = sum;
    __syncthreads();
    if (tid == 0) {
        float t = 0.0f;
        #pragma unroll
        for (int i = 0; i < 8; i++) t += red8[i];
        g_scabs[b] = t;
    }
}

// ======================================================================
// Kernel 2: gathered-A SGEMM, double-buffered.
//   P[m][j] = sum_k e_emb[idx_m][k] * Wc[k][j]
//   BM=128, BN=128, BK=16, 256 threads, TM=8 x TN=8 (n split tx*4 / 64+tx*4)
// ======================================================================
__global__ void __launch_bounds__(256, 2) k_gemm(
    const float* __restrict__ e_emb,
    const int* __restrict__ x, int xs)
{
    __shared__ float As[2][16][128];
    __shared__ float Bs[2][16][128];
    __shared__ int   idx_s[128];

    const int tid = threadIdx.x;
    const int bn = blockIdx.x * 128;
    const int bm = blockIdx.y * 128;

    if (tid < 128) {
        int gr = bm + tid;
        idx_s[tid] = (gr < BB) ? x[(gr * NCOL + 0) * xs]
                               : x[((gr - BB) * NCOL + 2) * xs];
    }
    __syncthreads();

    // A loads: thread -> row am = tid>>1, k offsets ak and ak+8 (ak = 0 or 4)
    const int am = tid >> 1;
    const int ak = (tid & 1) * 4;
    const float* aptr = e_emb + (size_t)idx_s[am] * 512;
    // B loads: k rows bk and bk+8, col bc
    const int bk = tid >> 5;           // 0..7
    const int bc = (tid & 31) * 4;     // 0..124

    const int tx = tid & 15;           // n
    const int ty = tid >> 4;           // m

    float acc[8][8];
    #pragma unroll
    for (int i = 0; i < 8; i++)
        #pragma unroll
        for (int j = 0; j < 8; j++) acc[i][j] = 0.0f;

    float4 a0, a1, b0, b1;

    // preload tile 0 into buffer 0
    a0 = *reinterpret_cast<const float4*>(aptr + ak);
    a1 = *reinterpret_cast<const float4*>(aptr + ak + 8);
    b0 = *reinterpret_cast<const float4*>(&g_Wc[(size_t)bk * 256 + bn + bc]);
    b1 = *reinterpret_cast<const float4*>(&g_Wc[(size_t)(bk + 8) * 256 + bn + bc]);
    As[0][ak + 0][am] = a0.x; As[0][ak + 1][am] = a0.y;
    As[0][ak + 2][am] = a0.z; As[0][ak + 3][am] = a0.w;
    As[0][ak + 8][am] = a1.x; As[0][ak + 9][am] = a1.y;
    As[0][ak + 10][am] = a1.z; As[0][ak + 11][am] = a1.w;
    *reinterpret_cast<float4*>(&Bs[0][bk][bc])     = b0;
    *reinterpret_cast<float4*>(&Bs[0][bk + 8][bc]) = b1;
    __syncthreads();

    int buf = 0;
    for (int k0 = 0; k0 < 512; k0 += 16) {
        const bool more = (k0 + 16 < 512);
        if (more) {
            a0 = *reinterpret_cast<const float4*>(aptr + k0 + 16 + ak);
            a1 = *reinterpret_cast<const float4*>(aptr + k0 + 16 + ak + 8);
            b0 = *reinterpret_cast<const float4*>(&g_Wc[(size_t)(k0 + 16 + bk) * 256 + bn + bc]);
            b1 = *reinterpret_cast<const float4*>(&g_Wc[(size_t)(k0 + 24 + bk) * 256 + bn + bc]);
        }

        #pragma unroll
        for (int k = 0; k < 16; k++) {
            float4 va0 = *reinterpret_cast<const float4*>(&As[buf][k][ty * 8]);
            float4 va1 = *reinterpret_cast<const float4*>(&As[buf][k][ty * 8 + 4]);
            float4 vb0 = *reinterpret_cast<const float4*>(&Bs[buf][k][tx * 4]);
            float4 vb1 = *reinterpret_cast<const float4*>(&Bs[buf][k][64 + tx * 4]);
            float av[8] = {va0.x, va0.y, va0.z, va0.w, va1.x, va1.y, va1.z, va1.w};
            float bv[8] = {vb0.x, vb0.y, vb0.z, vb0.w, vb1.x, vb1.y, vb1.z, vb1.w};
            #pragma unroll
            for (int i = 0; i < 8; i++)
                #pragma unroll
                for (int j = 0; j < 8; j++)
                    acc[i][j] = fmaf(av[i], bv[j], acc[i][j]);
        }

        if (more) {
            int nb = buf ^ 1;
            As[nb][ak + 0][am] = a0.x; As[nb][ak + 1][am] = a0.y;
            As[nb][ak + 2][am] = a0.z; As[nb][ak + 3][am] = a0.w;
            As[nb][ak + 8][am] = a1.x; As[nb][ak + 9][am] = a1.y;
            As[nb][ak + 10][am] = a1.z; As[nb][ak + 11][am] = a1.w;
            *reinterpret_cast<float4*>(&Bs[nb][bk][bc])     = b0;
            *reinterpret_cast<float4*>(&Bs[nb][bk + 8][bc]) = b1;
            __syncthreads();
            buf = nb;
        }
    }

    // epilogue: thread's n-cols are {bn + tx*4 + j} (j<4) and {bn + 64 + tx*4 + j-4}
    #pragma unroll
    for (int i = 0; i < 8; i++) {
        int row = bm + ty * 8 + i;
        float* dst = &g_P[(size_t)row * 256 + bn];
        *reinterpret_cast<float4*>(dst + tx * 4)      = make_float4(acc[i][0], acc[i][1], acc[i][2], acc[i][3]);
        *reinterpret_cast<float4*>(dst + 64 + tx * 4) = make_float4(acc[i][4], acc[i][5], acc[i][6], acc[i][7]);
    }
}

// ======================================================================
// Kernel 3: e_r_emb + sc_rel. Hybrid MUFU / bf16-smem-table.
// grid = 4 slices x 38 row-blocks = 152 blocks = 1 wave.
// Block: 512 thr = 16 warps; WARP = ONE ROW, lane = one d of the slice.
// Table read ts[ti*32 + lane] -> consecutive words -> conflict-free.
// ======================================================================
__global__ void __launch_bounds__(512, 1) k_rel() {
    extern __shared__ unsigned ts[];           // [1000*32] bf16x2 = 128 KB
    const int tid   = threadIdx.x;
    const int slice = blockIdx.x & 3;
    const int bj    = blockIdx.x >> 2;         // 0..37
    const int row_begin = bj * ROWS_PER_BLK;
    const int row_end   = min(BB, row_begin + ROWS_PER_BLK);

    // load this slice's table (contiguous 128 KB, coalesced)
    {
        const uint4* gt4 = reinterpret_cast<const uint4*>(g_Tb + (size_t)slice * 32000);
        uint4* ts4 = reinterpret_cast<uint4*>(ts);
        for (int i = tid; i < 8000; i += 512) ts4[i] = gt4[i];
    }
    __syncthreads();

    const int lane = tid & 31;
    const int wid  = tid >> 5;                 // warp = row lane
    const int d    = slice * 32 + lane;
    const float f  = exp2f(-(float)d * LOGK);

    for (int row = row_begin + wid; row < row_end; row += 16) {
        float acc[2][2];

        #pragma unroll
        for (int side = 0; side < 2; side++) {
            const float4* tw4 = reinterpret_cast<const float4*>(
                g_TW + (size_t)(side * BB + row) * 200);
            float re = 0.f, im = 0.f;

            // --- MUFU part (n in [0, NS)) : SFU pipe ---
            #pragma unroll 4
            for (int q = 0; q < NS / 2; q++) {
                float4 v = __ldg(&tw4[q]);     // (t0, w0, t1, w1), warp-broadcast
                float s, c;
                __sincosf(v.x * f, &s, &c); re = fmaf(v.y, c, re); im = fmaf(v.y, s, im);
                __sincosf(v.z * f, &s, &c); re = fmaf(v.w, c, re); im = fmaf(v.w, s, im);
            }
            // --- table part (n in [NS, 200)) : conflict-free LDS.32 ---
            #pragma unroll 4
            for (int q = NS / 2; q < 100; q++) {
                float4 v = __ldg(&tw4[q]);
                int t0 = (int)v.x, t1 = (int)v.z;
                __nv_bfloat162 h0 = *reinterpret_cast<const __nv_bfloat162*>(&ts[t0 * 32 + lane]);
                __nv_bfloat162 h1 = *reinterpret_cast<const __nv_bfloat162*>(&ts[t1 * 32 + lane]);
                float2 cs0 = __bfloat1622float2(h0);
                float2 cs1 = __bfloat1622float2(h1);
                re = fmaf(v.y, cs0.x, re); im = fmaf(v.y, cs0.y, im);
                re = fmaf(v.w, cs1.x, re); im = fmaf(v.w, cs1.y, im);
            }
            acc[side][0] = re; acc[side][1] = im;
        }

        // epilogue: add projection P, per-lane complex distance, warp reduce
        const float* Ps = g_P + (size_t)row * 256;
        const float* Po = g_P + (size_t)(BB + row) * 256;
        float dre = (acc[0][0] + Ps[d])       - (acc[1][0] + Po[d]);
        float dim = (acc[0][1] + Ps[d + 128]) - (acc[1][1] + Po[d + 128]);
        float v = sqrtf(dre * dre + dim * dim);

        #pragma unroll
        for (int off = 16; off; off >>= 1) v += __shfl_down_sync(0xffffffffu, v, off);
        if (lane == 0) g_prel[slice * BB + row] = v;
    }
}

// ======================================================================
// Kernel 4: final combine
// ======================================================================
__global__ void k_out(float* __restrict__ out) {
    int b = blockIdx.x * 256 + threadIdx.x;
    if (b < BB) {
        float s = g_scabs[b];
        #pragma unroll
        for (int i = 0; i < NSLICE; i++) s += g_prel[i * BB + b];
        out[b] = GAMMA_F - s;
    }
}

// ======================================================================
// launcher
// ======================================================================
extern "C" void kernel_launch(void* const* d_in, const int* in_sizes, int n_in,
                              void* d_out, int out_size)
{
    const int*   x     = (const int*)  d_in[0];
    const float* e_emb = (const float*)d_in[1];
    const float* r_emb = (const float*)d_in[2];
    const float* d_frq = (const float*)d_in[3];
    const float* d_phi = (const float*)d_in[4];
    const float* d_amp = (const float*)d_in[5];
    const float* m_frq = (const float*)d_in[6];
    const float* m_phi = (const float*)d_in[7];
    const float* m_amp = (const float*)d_in[8];
    const float* w_e   = (const float*)d_in[9];
    const float* w_rp  = (const float*)d_in[10];
    float* out = (float*)d_out;

    // x arrives as int64 reported in int32 words; infer element stride.
    int xs = in_sizes[0] / (BB * NCOL);
    if (xs < 1) xs = 1;

    cudaFuncSetAttribute(k_rel, cudaFuncAttributeMaxDynamicSharedMemorySize, 128 * 1024);

    k_wc<<<512, 256>>>(w_e);
    k_tbuild<<<1000, 128>>>();
    k_gather<<<BB, 256>>>(x, xs, e_emb, r_emb, d_frq, d_phi, d_amp,
                          m_frq, m_phi, m_amp, w_rp);
    k_gemm<<<dim3(2, 128), 256>>>(e_emb, x, xs);
    k_rel<<<NSLICE * RB, 512, 128000>>>();
    k_out<<<32, 256>>>(out);
}

// round 11
// speedup vs baseline: 1.4056x; 1.4056x over previous
#include <cuda_runtime.h>
#include <cuda_bf16.h>
#include <math.h>

// ---------------- problem constants ----------------
#define NE_    100000
#define NR_    200
#define RDIM_  384
#define BB     8192
#define NCOL   406          // 6 scalar cols + 2*NR
#define GAMMA_F 12.0f
#define TSLICE 4            // t in [0,1000) sliced into 4 ranges of 250
#define TSPAN  250
#define CAP    112          // bucket capacity per (row, side, slice); Binomial(200,1/4) tail ~1e-13
#define RB     38           // row-blocks per slice: 4*38 = 152 blocks = 1 wave on GB300
#define ROWS_PER_BLK 216    // ceil(8192/38)

// ---------------- scratch (__device__ globals; no allocs allowed) ----------------
__device__ float    g_Wc[512 * 256];                  // folded e_p_emb weight (512 KB)
__device__ float    g_P[2 * BB * 256];                // e_p: s rows [0,B), o rows [B,2B) (16 MB)
__device__ float    g_scabs[BB];                      // per-row sc_abs
__device__ float2   g_TWb[8 * BB * CAP];              // bucketed (t_local, w): [slice*2+side][row][CAP] (59 MB)
__device__ int      g_cnt[8 * BB];                    // bucket counts
__device__ unsigned g_Tb[1000 * 32 * 4];              // bf16x2 table: (t,lane) -> uint4 of 4 d's (512 KB)
__device__ float    g_part[8 * BB * 256];             // partial (re|im) per [slice*2+side][row] (64 MB)

#define LOGK (13.287712379549449f / 128.0f)           // log2(10000)/128

// ======================================================================
// Kernel 0a: fold w_e (512x128) into single real GEMM weight Wc (512x256)
// ======================================================================
__global__ void k_wc(const float* __restrict__ w_e) {
    int k = blockIdx.x;        // 0..511
    int j = threadIdx.x;       // 0..255
    float v;
    if (j < 128) {
        v = w_e[k * 128 + j];
        if (k >= 256) v = -v;
    } else {
        v = w_e[(k ^ 256) * 128 + (j - 128)];
        if (k < 256) v = -v;
    }
    g_Wc[k * 256 + j] = v;
}

// ======================================================================
// Kernel 0b: build bf16 pos-emb table.
// uint4 element (t, lane) holds d = 4*lane+k (k=0..3), word k = bf16x2(cos, sin).
// Slice s (t in [250s, 250s+250)) is a contiguous 128 KB region.
// ======================================================================
__global__ void k_tbuild() {
    int t = blockIdx.x;        // 0..999
    int d = threadIdx.x;       // 0..127
    float f = exp2f(-(float)d * LOGK);
    float s, c;
    sincosf((float)t * f, &s, &c);   // full-precision build (one-time)
    __nv_bfloat162 h2 = __floats2bfloat162_rn(c, s);
    g_Tb[(t * 32 + (d >> 2)) * 4 + (d & 3)] = *reinterpret_cast<unsigned*>(&h2);
}

// ======================================================================
// Kernel 1: per row — bucket (t,w) by t-slice, t_emb, sc_abs
// ======================================================================
__global__ void __launch_bounds__(256) k_gather(
    const int* __restrict__ x, int xs,
    const float* __restrict__ e_emb,
    const float* __restrict__ r_emb,
    const float* __restrict__ d_frq, const float* __restrict__ d_phi,
    const float* __restrict__ d_amp,
    const float* __restrict__ m_frq, const float* __restrict__ m_phi,
    const float* __restrict__ m_amp,
    const float* __restrict__ w_rp)
{
    __shared__ float st[256];
    __shared__ float ot[256];
    __shared__ float red8[8];
    __shared__ int   scnt[8];

    const int b   = blockIdx.x;
    const int tid = threadIdx.x;
    const int base = b * NCOL;

    if (tid < 8) scnt[tid] = 0;
    __syncthreads();

    const int s_idx = x[(base + 0) * xs];
    const int r_idx = x[(base + 1) * xs];
    const int o_idx = x[(base + 2) * xs];
    const float dv  = (float)x[(base + 3) * xs];
    const float mv  = (float)x[(base + 4) * xs];

    // ---- bucket (t_local, w) into g_TWb by t-slice ----
    for (int i = tid; i < 400; i += 256) {
        int side = (i >= 200);
        int n    = i - side * 200;
        int t    = x[(base + 6 + i) * xs];
        float w  = w_rp[r_idx * 200 + n];
        int slice = t / TSPAN;
        int idx8  = slice * 2 + side;
        int pos = atomicAdd(&scnt[idx8], 1);
        if (pos < CAP)
            g_TWb[((size_t)idx8 * BB + b) * CAP + pos] =
                make_float2((float)(t - slice * TSPAN), w);
    }

    // ---- t_emb (j = tid covers all 256 dims) ----
    {
        const int j  = tid;
        const int jm = (j < 128) ? j : (j - 128);
        {
            const size_t e = (size_t)s_idx;
            float angd = fmaf(dv, d_frq[e * 256 + j], d_phi[e * 256 + j]);
            float angm = fmaf(mv, m_frq[e * 256 + j], m_phi[e * 256 + j]);
            float ad = d_amp[e * 128 + jm];
            float am = m_amp[e * 128 + jm];
            st[j] = (j < 128) ? (ad * __cosf(angd) + am * __cosf(angm))
                              : (ad * __sinf(angd) + am * __sinf(angm));
        }
        {
            const size_t e = (size_t)o_idx;
            float angd = fmaf(dv, d_frq[e * 256 + j], d_phi[e * 256 + j]);
            float angm = fmaf(mv, m_frq[e * 256 + j], m_phi[e * 256 + j]);
            float ad = d_amp[e * 128 + jm];
            float am = m_amp[e * 128 + jm];
            ot[j] = (j < 128) ? (ad * __cosf(angd) + am * __cosf(angm))
                              : (ad * __sinf(angd) + am * __sinf(angm));
        }
    }
    __syncthreads();

    if (tid < 8) g_cnt[(size_t)tid * BB + b] = min(scnt[tid], CAP);

    // ---- sc_abs over k = 0..383 ----
    const float scale = (float)(3.141592653589793 / sqrt(6.0 / (double)(NR_ + RDIM_)));
    const size_t sb = (size_t)s_idx * 512;
    const size_t ob = (size_t)o_idx * 512;
    float sum = 0.0f;
    for (int k = tid; k < 384; k += 256) {
        float pr = r_emb[(size_t)r_idx * 384 + k] * scale;
        float sn, cs;
        __sincosf(pr, &sn, &cs);
        float re_s, im_s, re_o, im_o;
        if (k < 256) {
            re_s = e_emb[sb + k];
            im_s = e_emb[sb + 256 + k];
            re_o = e_emb[ob + k];
            im_o = e_emb[ob + 256 + k];
        } else {
            re_s = st[k - 256];  im_s = st[k - 128];
            re_o = ot[k - 256];  im_o = ot[k - 128];
        }
        float re = re_s * cs - im_s * sn - re_o;
        float im = re_s * sn + im_s * cs - im_o;
        sum += sqrtf(re * re + im * im);
    }

    #pragma unroll
    for (int off = 16; off; off >>= 1) sum += __shfl_down_sync(0xffffffffu, sum, off);
    if ((tid & 31) == 0) red8[tid >> 5] = sum;
    __syncthreads();
    if (tid == 0) {
        float t = 0.0f;
        #pragma unroll
        for (int i = 0; i < 8; i++) t += red8[i];
        g_scabs[b] = t;
    }
}

// ======================================================================
// Kernel 2: gathered-A SGEMM, double-buffered (measured 102 us; unchanged)
// ======================================================================
__global__ void __launch_bounds__(256, 2) k_gemm(
    const float* __restrict__ e_emb,
    const int* __restrict__ x, int xs)
{
    __shared__ float As[2][16][128];
    __shared__ float Bs[2][16][128];
    __shared__ int   idx_s[128];

    const int tid = threadIdx.x;
    const int bn = blockIdx.x * 128;
    const int bm = blockIdx.y * 128;

    if (tid < 128) {
        int gr = bm + tid;
        idx_s[tid] = (gr < BB) ? x[(gr * NCOL + 0) * xs]
                               : x[((gr - BB) * NCOL + 2) * xs];
    }
    __syncthreads();

    const int am = tid >> 1;
    const int ak = (tid & 1) * 4;
    const float* aptr = e_emb + (size_t)idx_s[am] * 512;
    const int bk = tid >> 5;
    const int bc = (tid & 31) * 4;
    const int tx = tid & 15;
    const int ty = tid >> 4;

    float acc[8][8];
    #pragma unroll
    for (int i = 0; i < 8; i++)
        #pragma unroll
        for (int j = 0; j < 8; j++) acc[i][j] = 0.0f;

    float4 a0, a1, b0, b1;

    a0 = *reinterpret_cast<const float4*>(aptr + ak);
    a1 = *reinterpret_cast<const float4*>(aptr + ak + 8);
    b0 = *reinterpret_cast<const float4*>(&g_Wc[(size_t)bk * 256 + bn + bc]);
    b1 = *reinterpret_cast<const float4*>(&g_Wc[(size_t)(bk + 8) * 256 + bn + bc]);
    As[0][ak + 0][am] = a0.x; As[0][ak + 1][am] = a0.y;
    As[0][ak + 2][am] = a0.z; As[0][ak + 3][am] = a0.w;
    As[0][ak + 8][am] = a1.x; As[0][ak + 9][am] = a1.y;
    As[0][ak + 10][am] = a1.z; As[0][ak + 11][am] = a1.w;
    *reinterpret_cast<float4*>(&Bs[0][bk][bc])     = b0;
    *reinterpret_cast<float4*>(&Bs[0][bk + 8][bc]) = b1;
    __syncthreads();

    int buf = 0;
    for (int k0 = 0; k0 < 512; k0 += 16) {
        const bool more = (k0 + 16 < 512);
        if (more) {
            a0 = *reinterpret_cast<const float4*>(aptr + k0 + 16 + ak);
            a1 = *reinterpret_cast<const float4*>(aptr + k0 + 16 + ak + 8);
            b0 = *reinterpret_cast<const float4*>(&g_Wc[(size_t)(k0 + 16 + bk) * 256 + bn + bc]);
            b1 = *reinterpret_cast<const float4*>(&g_Wc[(size_t)(k0 + 24 + bk) * 256 + bn + bc]);
        }

        #pragma unroll
        for (int k = 0; k < 16; k++) {
            float4 va0 = *reinterpret_cast<const float4*>(&As[buf][k][ty * 8]);
            float4 va1 = *reinterpret_cast<const float4*>(&As[buf][k][ty * 8 + 4]);
            float4 vb0 = *reinterpret_cast<const float4*>(&Bs[buf][k][tx * 4]);
            float4 vb1 = *reinterpret_cast<const float4*>(&Bs[buf][k][64 + tx * 4]);
            float av[8] = {va0.x, va0.y, va0.z, va0.w, va1.x, va1.y, va1.z, va1.w};
            float bv[8] = {vb0.x, vb0.y, vb0.z, vb0.w, vb1.x, vb1.y, vb1.z, vb1.w};
            #pragma unroll
            for (int i = 0; i < 8; i++)
                #pragma unroll
                for (int j = 0; j < 8; j++)
                    acc[i][j] = fmaf(av[i], bv[j], acc[i][j]);
        }

        if (more) {
            int nb = buf ^ 1;
            As[nb][ak + 0][am] = a0.x; As[nb][ak + 1][am] = a0.y;
            As[nb][ak + 2][am] = a0.z; As[nb][ak + 3][am] = a0.w;
            As[nb][ak + 8][am] = a1.x; As[nb][ak + 9][am] = a1.y;
            As[nb][ak + 10][am] = a1.z; As[nb][ak + 11][am] = a1.w;
            *reinterpret_cast<float4*>(&Bs[nb][bk][bc])     = b0;
            *reinterpret_cast<float4*>(&Bs[nb][bk + 8][bc]) = b1;
            __syncthreads();
            buf = nb;
        }
    }

    #pragma unroll
    for (int i = 0; i < 8; i++) {
        int row = bm + ty * 8 + i;
        float* dst = &g_P[(size_t)row * 256 + bn];
        *reinterpret_cast<float4*>(dst + tx * 4)      = make_float4(acc[i][0], acc[i][1], acc[i][2], acc[i][3]);
        *reinterpret_cast<float4*>(dst + 64 + tx * 4) = make_float4(acc[i][4], acc[i][5], acc[i][6], acc[i][7]);
    }
}

// ======================================================================
// Kernel 3: e_r_emb partials, t-sliced bf16 table.
// grid = 4 t-slices x 38 row-blocks = 152 blocks = 1 wave.
// Block: 512 thr = 16 warps; WARP = ONE ROW, lane covers 4 d's (uint4).
// ts[t_local*32 + lane]: warp reads 512B contiguous -> 4 wf, conflict-free,
// one LDS.128 serves 128 d's for one n.
// ======================================================================
__global__ void __launch_bounds__(512, 1) k_rel() {
    extern __shared__ uint4 ts[];              // [250*32] uint4 = 128 KB
    const int tid   = threadIdx.x;
    const int slice = blockIdx.x & 3;
    const int bj    = blockIdx.x >> 2;         // 0..37
    const int row_begin = bj * ROWS_PER_BLK;
    const int row_end   = min(BB, row_begin + ROWS_PER_BLK);

    // load this t-slice's table (contiguous 128 KB, coalesced)
    {
        const uint4* gt4 = reinterpret_cast<const uint4*>(g_Tb) + (size_t)slice * 8000;
        for (int i = tid; i < 8000; i += 512) ts[i] = gt4[i];
    }
    __syncthreads();

    const int lane = tid & 31;
    const int wid  = tid >> 5;

    for (int row = row_begin + wid; row < row_end; row += 16) {
        #pragma unroll
        for (int side = 0; side < 2; side++) {
            const int idx8 = slice * 2 + side;
            const int cnt  = g_cnt[(size_t)idx8 * BB + row];
            const float2* tw = g_TWb + ((size_t)idx8 * BB + row) * CAP;

            float re0 = 0.f, im0 = 0.f, re1 = 0.f, im1 = 0.f;
            float re2 = 0.f, im2 = 0.f, re3 = 0.f, im3 = 0.f;

            int i = 0;
            #pragma unroll 2
            for (; i + 2 <= cnt; i += 2) {
                float4 v = __ldg(reinterpret_cast<const float4*>(tw + i)); // broadcast
                {
                    uint4 q = ts[(int)v.x * 32 + lane];
                    float2 c0 = __bfloat1622float2(*reinterpret_cast<__nv_bfloat162*>(&q.x));
                    float2 c1 = __bfloat1622float2(*reinterpret_cast<__nv_bfloat162*>(&q.y));
                    float2 c2 = __bfloat1622float2(*reinterpret_cast<__nv_bfloat162*>(&q.z));
                    float2 c3 = __bfloat1622float2(*reinterpret_cast<__nv_bfloat162*>(&q.w));
                    re0 = fmaf(v.y, c0.x, re0); im0 = fmaf(v.y, c0.y, im0);
                    re1 = fmaf(v.y, c1.x, re1); im1 = fmaf(v.y, c1.y, im1);
                    re2 = fmaf(v.y, c2.x, re2); im2 = fmaf(v.y, c2.y, im2);
                    re3 = fmaf(v.y, c3.x, re3); im3 = fmaf(v.y, c3.y, im3);
                }
                {
                    uint4 q = ts[(int)v.z * 32 + lane];
                    float2 c0 = __bfloat1622float2(*reinterpret_cast<__nv_bfloat162*>(&q.x));
                    float2 c1 = __bfloat1622float2(*reinterpret_cast<__nv_bfloat162*>(&q.y));
                    float2 c2 = __bfloat1622float2(*reinterpret_cast<__nv_bfloat162*>(&q.z));
                    float2 c3 = __bfloat1622float2(*reinterpret_cast<__nv_bfloat162*>(&q.w));
                    re0 = fmaf(v.w, c0.x, re0); im0 = fmaf(v.w, c0.y, im0);
                    re1 = fmaf(v.w, c1.x, re1); im1 = fmaf(v.w, c1.y, im1);
                    re2 = fmaf(v.w, c2.x, re2); im2 = fmaf(v.w, c2.y, im2);
                    re3 = fmaf(v.w, c3.x, re3); im3 = fmaf(v.w, c3.y, im3);
                }
            }
            if (i < cnt) {
                float2 v = __ldg(tw + i);
                uint4 q = ts[(int)v.x * 32 + lane];
                float2 c0 = __bfloat1622float2(*reinterpret_cast<__nv_bfloat162*>(&q.x));
                float2 c1 = __bfloat1622float2(*reinterpret_cast<__nv_bfloat162*>(&q.y));
                float2 c2 = __bfloat1622float2(*reinterpret_cast<__nv_bfloat162*>(&q.z));
                float2 c3 = __bfloat1622float2(*reinterpret_cast<__nv_bfloat162*>(&q.w));
                re0 = fmaf(v.y, c0.x, re0); im0 = fmaf(v.y, c0.y, im0);
                re1 = fmaf(v.y, c1.x, re1); im1 = fmaf(v.y, c1.y, im1);
                re2 = fmaf(v.y, c2.x, re2); im2 = fmaf(v.y, c2.y, im2);
                re3 = fmaf(v.y, c3.x, re3); im3 = fmaf(v.y, c3.y, im3);
            }

            // partials: re at d=4*lane..+3, im at 128+4*lane..+3 (coalesced STG.128)
            float* dst = g_part + ((size_t)idx8 * BB + row) * 256;
            *reinterpret_cast<float4*>(dst + 4 * lane)       = make_float4(re0, re1, re2, re3);
            *reinterpret_cast<float4*>(dst + 128 + 4 * lane) = make_float4(im0, im1, im2, im3);
        }
    }
}

// ======================================================================
// Kernel 4: combine — sum partials over t-slices, add P, sqrt, reduce, output
// ======================================================================
__global__ void __launch_bounds__(128) k_comb(float* __restrict__ out) {
    __shared__ float red4[4];
    const int row = blockIdx.x;
    const int d   = threadIdx.x;   // 0..127

    float rs = 0.f, is = 0.f, ro = 0.f, io = 0.f;
    #pragma unroll
    for (int t = 0; t < TSLICE; t++) {
        const float* ps = g_part + ((size_t)(t * 2 + 0) * BB + row) * 256;
        const float* po = g_part + ((size_t)(t * 2 + 1) * BB + row) * 256;
        rs += ps[d]; is += ps[128 + d];
        ro += po[d]; io += po[128 + d];
    }
    const float* Ps = g_P + (size_t)row * 256;
    const float* Po = g_P + (size_t)(BB + row) * 256;
    rs += Ps[d]; is += Ps[128 + d];
    ro += Po[d]; io += Po[128 + d];

    float dre = rs - ro, dim = is - io;
    float v = sqrtf(dre * dre + dim * dim);

    #pragma unroll
    for (int off = 16; off; off >>= 1) v += __shfl_down_sync(0xffffffffu, v, off);
    if ((d & 31) == 0) red4[d >> 5] = v;
    __syncthreads();
    if (d == 0)
        out[row] = GAMMA_F - (g_scabs[row] + red4[0] + red4[1] + red4[2] + red4[3]);
}

// ======================================================================
// launcher
// ======================================================================
extern "C" void kernel_launch(void* const* d_in, const int* in_sizes, int n_in,
                              void* d_out, int out_size)
{
    const int*   x     = (const int*)  d_in[0];
    const float* e_emb = (const float*)d_in[1];
    const float* r_emb = (const float*)d_in[2];
    const float* d_frq = (const float*)d_in[3];
    const float* d_phi = (const float*)d_in[4];
    const float* d_amp = (const float*)d_in[5];
    const float* m_frq = (const float*)d_in[6];
    const float* m_phi = (const float*)d_in[7];
    const float* m_amp = (const float*)d_in[8];
    const float* w_e   = (const float*)d_in[9];
    const float* w_rp  = (const float*)d_in[10];
    float* out = (float*)d_out;

    // x arrives as int64 reported in int32 words; infer element stride.
    int xs = in_sizes[0] / (BB * NCOL);
    if (xs < 1) xs = 1;

    cudaFuncSetAttribute(k_rel, cudaFuncAttributeMaxDynamicSharedMemorySize, 128 * 1024);

    k_wc<<<512, 256>>>(w_e);
    k_tbuild<<<1000, 128>>>();
    k_gather<<<BB, 256>>>(x, xs, e_emb, r_emb, d_frq, d_phi, d_amp,
                          m_frq, m_phi, m_amp, w_rp);
    k_gemm<<<dim3(2, 128), 256>>>(e_emb, x, xs);
    k_rel<<<TSLICE * RB, 512, 128 * 1024>>>();
    k_comb<<<BB, 128>>>(out);
}

// round 13
// speedup vs baseline: 1.7307x; 1.2313x over previous
#include <cuda_runtime.h>
#include <cuda_bf16.h>
#include <math.h>
#include <stdint.h>

// ---------------- problem constants ----------------
#define NE_    100000
#define NR_    200
#define RDIM_  384
#define BB     8192
#define NCOL   406          // 6 scalar cols + 2*NR
#define GAMMA_F 12.0f
#define TSLICE 4            // t in [0,1000) sliced into 4 ranges of 250
#define TSPAN  250
#define CAP    112          // bucket capacity per (row, side, slice)
#define RB     38           // row-blocks per slice: 4*38 = 152 blocks = 1 wave
#define ROWS_PER_BLK 216

#define LOGK (13.287712379549449f / 128.0f)   // log2(10000)/128

// ---------------- scratch (__device__ globals; no allocs allowed) ----------------
__device__ float    g_P[2 * BB * 256];               // e_p: s rows [0,B), o rows [B,2B) (16 MB)
__device__ float    g_scabs[BB];                     // per-row sc_abs
__device__ float2   g_TWb[8 * BB * CAP];             // bucketed (t_local, w) (59 MB)
__device__ int      g_cnt[8 * BB];                   // bucket counts
__device__ unsigned g_Tb[1000 * 32 * 4];             // bf16x2 table: (t,lane)->uint4 of 4 d's (512 KB)
__device__ float    g_part[8 * BB * 256];            // partials per [slice*2+side][row] (64 MB)
__device__ __align__(16) __nv_bfloat16 g_WcT[256 * 512];  // bf16 B^T: WcT[n][k] (256 KB)

// ======================================================================
// Kernel 0a: fold w_e into bf16 transposed GEMM weight WcT[n][k] = Wc[k][n]
//   n <  128 : Wc[k][n] = (k<256 ?  +1 : -1) * w_e[k][n]
//   n >= 128 : Wc[k][n] = (k<256 ?  -1 : +1) * w_e[k^256][n-128]
// ======================================================================
__global__ void k_wct(const float* __restrict__ w_e) {
    int n = blockIdx.x;        // 0..255
    int k = threadIdx.x;       // 0..511
    float v;
    if (n < 128) {
        v = w_e[k * 128 + n];
        if (k >= 256) v = -v;
    } else {
        v = w_e[(k ^ 256) * 128 + (n - 128)];
        if (k < 256) v = -v;
    }
    g_WcT[n * 512 + k] = __float2bfloat16(v);
}

// ======================================================================
// Kernel 0b: build bf16 pos-emb table (t-slice-major; see R11)
// ======================================================================
__global__ void k_tbuild() {
    int t = blockIdx.x;        // 0..999
    int d = threadIdx.x;       // 0..127
    float f = exp2f(-(float)d * LOGK);
    float s, c;
    sincosf((float)t * f, &s, &c);
    __nv_bfloat162 h2 = __floats2bfloat162_rn(c, s);
    g_Tb[(t * 32 + (d >> 2)) * 4 + (d & 3)] = *reinterpret_cast<unsigned*>(&h2);
}

// ======================================================================
// Kernel 1: per row — bucket (t,w) by t-slice, t_emb, sc_abs  (unchanged)
// ======================================================================
__global__ void __launch_bounds__(256) k_gather(
    const int* __restrict__ x, int xs,
    const float* __restrict__ e_emb,
    const float* __restrict__ r_emb,
    const float* __restrict__ d_frq, const float* __restrict__ d_phi,
    const float* __restrict__ d_amp,
    const float* __restrict__ m_frq, const float* __restrict__ m_phi,
    const float* __restrict__ m_amp,
    const float* __restrict__ w_rp)
{
    __shared__ float st[256];
    __shared__ float ot[256];
    __shared__ float red8[8];
    __shared__ int   scnt[8];

    const int b   = blockIdx.x;
    const int tid = threadIdx.x;
    const int base = b * NCOL;

    if (tid < 8) scnt[tid] = 0;
    __syncthreads();

    const int s_idx = x[(base + 0) * xs];
    const int r_idx = x[(base + 1) * xs];
    const int o_idx = x[(base + 2) * xs];
    const float dv  = (float)x[(base + 3) * xs];
    const float mv  = (float)x[(base + 4) * xs];

    for (int i = tid; i < 400; i += 256) {
        int side = (i >= 200);
        int n    = i - side * 200;
        int t    = x[(base + 6 + i) * xs];
        float w  = w_rp[r_idx * 200 + n];
        int slice = t / TSPAN;
        int idx8  = slice * 2 + side;
        int pos = atomicAdd(&scnt[idx8], 1);
        if (pos < CAP)
            g_TWb[((size_t)idx8 * BB + b) * CAP + pos] =
                make_float2((float)(t - slice * TSPAN), w);
    }

    {
        const int j  = tid;
        const int jm = (j < 128) ? j : (j - 128);
        {
            const size_t e = (size_t)s_idx;
            float angd = fmaf(dv, d_frq[e * 256 + j], d_phi[e * 256 + j]);
            float angm = fmaf(mv, m_frq[e * 256 + j], m_phi[e * 256 + j]);
            float ad = d_amp[e * 128 + jm];
            float am = m_amp[e * 128 + jm];
            st[j] = (j < 128) ? (ad * __cosf(angd) + am * __cosf(angm))
                              : (ad * __sinf(angd) + am * __sinf(angm));
        }
        {
            const size_t e = (size_t)o_idx;
            float angd = fmaf(dv, d_frq[e * 256 + j], d_phi[e * 256 + j]);
            float angm = fmaf(mv, m_frq[e * 256 + j], m_phi[e * 256 + j]);
            float ad = d_amp[e * 128 + jm];
            float am = m_amp[e * 128 + jm];
            ot[j] = (j < 128) ? (ad * __cosf(angd) + am * __cosf(angm))
                              : (ad * __sinf(angd) + am * __sinf(angm));
        }
    }
    __syncthreads();

    if (tid < 8) g_cnt[(size_t)tid * BB + b] = min(scnt[tid], CAP);

    const float scale = (float)(3.141592653589793 / sqrt(6.0 / (double)(NR_ + RDIM_)));
    const size_t sb = (size_t)s_idx * 512;
    const size_t ob = (size_t)o_idx * 512;
    float sum = 0.0f;
    for (int k = tid; k < 384; k += 256) {
        float pr = r_emb[(size_t)r_idx * 384 + k] * scale;
        float sn, cs;
        __sincosf(pr, &sn, &cs);
        float re_s, im_s, re_o, im_o;
        if (k < 256) {
            re_s = e_emb[sb + k];
            im_s = e_emb[sb + 256 + k];
            re_o = e_emb[ob + k];
            im_o = e_emb[ob + 256 + k];
        } else {
            re_s = st[k - 256];  im_s = st[k - 128];
            re_o = ot[k - 256];  im_o = ot[k - 128];
        }
        float re = re_s * cs - im_s * sn - re_o;
        float im = re_s * sn + im_s * cs - im_o;
        sum += sqrtf(re * re + im * im);
    }

    #pragma unroll
    for (int off = 16; off; off >>= 1) sum += __shfl_down_sync(0xffffffffu, sum, off);
    if ((tid & 31) == 0) red8[tid >> 5] = sum;
    __syncthreads();
    if (tid == 0) {
        float t = 0.0f;
        #pragma unroll
        for (int i = 0; i < 8; i++) t += red8[i];
        g_scabs[b] = t;
    }
}

// ======================================================================
// Kernel 2: gathered-A bf16 HMMA GEMM via mma.sync.m16n8k16 (fp32 acc).
//   P[m][n] = sum_k A[m][k] * WcT[n][k]
//   BM=128, BN=128, BK=32, 256 threads (8 warps), warp tile 64x32 (4x4 frags)
//   smem tiles padded to 40 bf16/row -> conflict-free fragment loads.
// ======================================================================
#define PADK 40

__device__ __forceinline__ void mma16816(float* c, const uint32_t* a, const uint32_t* b) {
    asm volatile(
        "mma.sync.aligned.m16n8k16.row.col.f32.bf16.bf16.f32 "
        "{%0,%1,%2,%3}, {%4,%5,%6,%7}, {%8,%9}, {%0,%1,%2,%3};"
        : "+f"(c[0]), "+f"(c[1]), "+f"(c[2]), "+f"(c[3])
        : "r"(a[0]), "r"(a[1]), "r"(a[2]), "r"(a[3]), "r"(b[0]), "r"(b[1]));
}

__global__ void __launch_bounds__(256) k_gemm_mma(
    const float* __restrict__ e_emb,
    const int* __restrict__ x, int xs)
{
    __shared__ __nv_bfloat16 As[128 * PADK];   // 10 KB
    __shared__ __nv_bfloat16 Bs[128 * PADK];   // 10 KB
    __shared__ int idx_s[128];

    const int tid  = threadIdx.x;
    const int wid  = tid >> 5;
    const int lane = tid & 31;
    const int bn = blockIdx.x * 128;
    const int bm = blockIdx.y * 128;

    if (tid < 128) {
        int gr = bm + tid;
        idx_s[tid] = (gr < BB) ? x[(gr * NCOL + 0) * xs]
                               : x[((gr - BB) * NCOL + 2) * xs];
    }
    __syncthreads();

    // warp tile: wm in {0,1} (64 rows), wn in {0..3} (32 cols)
    const int wm = wid & 1;
    const int wn = wid >> 1;
    const int gid = lane >> 2;          // 0..7
    const int tig = lane & 3;           // 0..3

    // staging assignments
    const int sr = tid >> 1;            // A row / B n-row (0..127)
    const int sk = (tid & 1) * 16;      // k half (0 or 16)
    const float4* aptr = reinterpret_cast<const float4*>(
        e_emb + (size_t)idx_s[sr] * 512);
    const uint4* bptr = reinterpret_cast<const uint4*>(
        g_WcT + (size_t)(bn + sr) * 512);

    float acc[4][4][4];
    #pragma unroll
    for (int i = 0; i < 4; i++)
        #pragma unroll
        for (int j = 0; j < 4; j++)
            #pragma unroll
            for (int e = 0; e < 4; e++) acc[i][j][e] = 0.0f;

    for (int k0 = 0; k0 < 512; k0 += 32) {
        // ---- stage A (fp32 -> bf16) ----
        {
            float4 f0 = __ldg(aptr + ((k0 + sk) >> 2) + 0);
            float4 f1 = __ldg(aptr + ((k0 + sk) >> 2) + 1);
            float4 f2 = __ldg(aptr + ((k0 + sk) >> 2) + 2);
            float4 f3 = __ldg(aptr + ((k0 + sk) >> 2) + 3);
            __nv_bfloat162 h0 = __floats2bfloat162_rn(f0.x, f0.y);
            __nv_bfloat162 h1 = __floats2bfloat162_rn(f0.z, f0.w);
            __nv_bfloat162 h2 = __floats2bfloat162_rn(f1.x, f1.y);
            __nv_bfloat162 h3 = __floats2bfloat162_rn(f1.z, f1.w);
            __nv_bfloat162 h4 = __floats2bfloat162_rn(f2.x, f2.y);
            __nv_bfloat162 h5 = __floats2bfloat162_rn(f2.z, f2.w);
            __nv_bfloat162 h6 = __floats2bfloat162_rn(f3.x, f3.y);
            __nv_bfloat162 h7 = __floats2bfloat162_rn(f3.z, f3.w);
            uint4 q0, q1;
            q0.x = *reinterpret_cast<unsigned*>(&h0);
            q0.y = *reinterpret_cast<unsigned*>(&h1);
            q0.z = *reinterpret_cast<unsigned*>(&h2);
            q0.w = *reinterpret_cast<unsigned*>(&h3);
            q1.x = *reinterpret_cast<unsigned*>(&h4);
            q1.y = *reinterpret_cast<unsigned*>(&h5);
            q1.z = *reinterpret_cast<unsigned*>(&h6);
            q1.w = *reinterpret_cast<unsigned*>(&h7);
            *reinterpret_cast<uint4*>(&As[sr * PADK + sk])     = q0;
            *reinterpret_cast<uint4*>(&As[sr * PADK + sk + 8]) = q1;
        }
        // ---- stage B (bf16 copy) ----
        {
            uint4 q0 = __ldg(bptr + ((k0 + sk) >> 3) + 0);
            uint4 q1 = __ldg(bptr + ((k0 + sk) >> 3) + 1);
            *reinterpret_cast<uint4*>(&Bs[sr * PADK + sk])     = q0;
            *reinterpret_cast<uint4*>(&Bs[sr * PADK + sk + 8]) = q1;
        }
        __syncthreads();

        #pragma unroll
        for (int ks = 0; ks < 32; ks += 16) {
            uint32_t afr[4][4], bfr[4][2];
            #pragma unroll
            for (int i = 0; i < 4; i++) {
                int row = wm * 64 + i * 16 + gid;
                afr[i][0] = *reinterpret_cast<const uint32_t*>(&As[row * PADK + ks + tig * 2]);
                afr[i][1] = *reinterpret_cast<const uint32_t*>(&As[(row + 8) * PADK + ks + tig * 2]);
                afr[i][2] = *reinterpret_cast<const uint32_t*>(&As[row * PADK + ks + 8 + tig * 2]);
                afr[i][3] = *reinterpret_cast<const uint32_t*>(&As[(row + 8) * PADK + ks + 8 + tig * 2]);
            }
            #pragma unroll
            for (int j = 0; j < 4; j++) {
                int nc = wn * 32 + j * 8 + gid;
                bfr[j][0] = *reinterpret_cast<const uint32_t*>(&Bs[nc * PADK + ks + tig * 2]);
                bfr[j][1] = *reinterpret_cast<const uint32_t*>(&Bs[nc * PADK + ks + 8 + tig * 2]);
            }
            #pragma unroll
            for (int i = 0; i < 4; i++)
                #pragma unroll
                for (int j = 0; j < 4; j++)
                    mma16816(acc[i][j], afr[i], bfr[j]);
        }
        __syncthreads();
    }

    // ---- epilogue: c0/c1 at (m, n..n+1), c2/c3 at (m+8, n..n+1) ----
    #pragma unroll
    for (int i = 0; i < 4; i++) {
        int row = bm + wm * 64 + i * 16 + gid;
        #pragma unroll
        for (int j = 0; j < 4; j++) {
            int col = bn + wn * 32 + j * 8 + tig * 2;
            *reinterpret_cast<float2*>(&g_P[(size_t)row * 256 + col]) =
                make_float2(acc[i][j][0], acc[i][j][1]);
            *reinterpret_cast<float2*>(&g_P[(size_t)(row + 8) * 256 + col]) =
                make_float2(acc[i][j][2], acc[i][j][3]);
        }
    }
}

// ======================================================================
// Kernel 3: e_r_emb partials, t-sliced bf16 table (unchanged from R11)
// ======================================================================
__global__ void __launch_bounds__(512, 1) k_rel() {
    extern __shared__ uint4 ts[];              // [250*32] uint4 = 128 KB
    const int tid   = threadIdx.x;
    const int slice = blockIdx.x & 3;
    const int bj    = blockIdx.x >> 2;         // 0..37
    const int row_begin = bj * ROWS_PER_BLK;
    const int row_end   = min(BB, row_begin + ROWS_PER_BLK);

    {
        const uint4* gt4 = reinterpret_cast<const uint4*>(g_Tb) + (size_t)slice * 8000;
        for (int i = tid; i < 8000; i += 512) ts[i] = gt4[i];
    }
    __syncthreads();

    const int lane = tid & 31;
    const int wid  = tid >> 5;

    for (int row = row_begin + wid; row < row_end; row += 16) {
        #pragma unroll
        for (int side = 0; side < 2; side++) {
            const int idx8 = slice * 2 + side;
            const int cnt  = g_cnt[(size_t)idx8 * BB + row];
            const float2* tw = g_TWb + ((size_t)idx8 * BB + row) * CAP;

            float re0 = 0.f, im0 = 0.f, re1 = 0.f, im1 = 0.f;
            float re2 = 0.f, im2 = 0.f, re3 = 0.f, im3 = 0.f;

            int i = 0;
            #pragma unroll 2
            for (; i + 2 <= cnt; i += 2) {
                float4 v = __ldg(reinterpret_cast<const float4*>(tw + i));
                {
                    uint4 q = ts[(int)v.x * 32 + lane];
                    float2 c0 = __bfloat1622float2(*reinterpret_cast<__nv_bfloat162*>(&q.x));
                    float2 c1 = __bfloat1622float2(*reinterpret_cast<__nv_bfloat162*>(&q.y));
                    float2 c2 = __bfloat1622float2(*reinterpret_cast<__nv_bfloat162*>(&q.z));
                    float2 c3 = __bfloat1622float2(*reinterpret_cast<__nv_bfloat162*>(&q.w));
                    re0 = fmaf(v.y, c0.x, re0); im0 = fmaf(v.y, c0.y, im0);
                    re1 = fmaf(v.y, c1.x, re1); im1 = fmaf(v.y, c1.y, im1);
                    re2 = fmaf(v.y, c2.x, re2); im2 = fmaf(v.y, c2.y, im2);
                    re3 = fmaf(v.y, c3.x, re3); im3 = fmaf(v.y, c3.y, im3);
                }
                {
                    uint4 q = ts[(int)v.z * 32 + lane];
                    float2 c0 = __bfloat1622float2(*reinterpret_cast<__nv_bfloat162*>(&q.x));
                    float2 c1 = __bfloat1622float2(*reinterpret_cast<__nv_bfloat162*>(&q.y));
                    float2 c2 = __bfloat1622float2(*reinterpret_cast<__nv_bfloat162*>(&q.z));
                    float2 c3 = __bfloat1622float2(*reinterpret_cast<__nv_bfloat162*>(&q.w));
                    re0 = fmaf(v.w, c0.x, re0); im0 = fmaf(v.w, c0.y, im0);
                    re1 = fmaf(v.w, c1.x, re1); im1 = fmaf(v.w, c1.y, im1);
                    re2 = fmaf(v.w, c2.x, re2); im2 = fmaf(v.w, c2.y, im2);
                    re3 = fmaf(v.w, c3.x, re3); im3 = fmaf(v.w, c3.y, im3);
                }
            }
            if (i < cnt) {
                float2 v = __ldg(tw + i);
                uint4 q = ts[(int)v.x * 32 + lane];
                float2 c0 = __bfloat1622float2(*reinterpret_cast<__nv_bfloat162*>(&q.x));
                float2 c1 = __bfloat1622float2(*reinterpret_cast<__nv_bfloat162*>(&q.y));
                float2 c2 = __bfloat1622float2(*reinterpret_cast<__nv_bfloat162*>(&q.z));
                float2 c3 = __bfloat1622float2(*reinterpret_cast<__nv_bfloat162*>(&q.w));
                re0 = fmaf(v.y, c0.x, re0); im0 = fmaf(v.y, c0.y, im0);
                re1 = fmaf(v.y, c1.x, re1); im1 = fmaf(v.y, c1.y, im1);
                re2 = fmaf(v.y, c2.x, re2); im2 = fmaf(v.y, c2.y, im2);
                re3 = fmaf(v.y, c3.x, re3); im3 = fmaf(v.y, c3.y, im3);
            }

            float* dst = g_part + ((size_t)idx8 * BB + row) * 256;
            *reinterpret_cast<float4*>(dst + 4 * lane)       = make_float4(re0, re1, re2, re3);
            *reinterpret_cast<float4*>(dst + 128 + 4 * lane) = make_float4(im0, im1, im2, im3);
        }
    }
}

// ======================================================================
// Kernel 4: combine (unchanged from R11)
// ======================================================================
__global__ void __launch_bounds__(128) k_comb(float* __restrict__ out) {
    __shared__ float red4[4];
    const int row = blockIdx.x;
    const int d   = threadIdx.x;   // 0..127

    float rs = 0.f, is = 0.f, ro = 0.f, io = 0.f;
    #pragma unroll
    for (int t = 0; t < TSLICE; t++) {
        const float* ps = g_part + ((size_t)(t * 2 + 0) * BB + row) * 256;
        const float* po = g_part + ((size_t)(t * 2 + 1) * BB + row) * 256;
        rs += ps[d]; is += ps[128 + d];
        ro += po[d]; io += po[128 + d];
    }
    const float* Ps = g_P + (size_t)row * 256;
    const float* Po = g_P + (size_t)(BB + row) * 256;
    rs += Ps[d]; is += Ps[128 + d];
    ro += Po[d]; io += Po[128 + d];

    float dre = rs - ro, dim = is - io;
    float v = sqrtf(dre * dre + dim * dim);

    #pragma unroll
    for (int off = 16; off; off >>= 1) v += __shfl_down_sync(0xffffffffu, v, off);
    if ((d & 31) == 0) red4[d >> 5] = v;
    __syncthreads();
    if (d == 0)
        out[row] = GAMMA_F - (g_scabs[row] + red4[0] + red4[1] + red4[2] + red4[3]);
}

// ======================================================================
// launcher
// ======================================================================
extern "C" void kernel_launch(void* const* d_in, const int* in_sizes, int n_in,
                              void* d_out, int out_size)
{
    const int*   x     = (const int*)  d_in[0];
    const float* e_emb = (const float*)d_in[1];
    const float* r_emb = (const float*)d_in[2];
    const float* d_frq = (const float*)d_in[3];
    const float* d_phi = (const float*)d_in[4];
    const float* d_amp = (const float*)d_in[5];
    const float* m_frq = (const float*)d_in[6];
    const float* m_phi = (const float*)d_in[7];
    const float* m_amp = (const float*)d_in[8];
    const float* w_e   = (const float*)d_in[9];
    const float* w_rp  = (const float*)d_in[10];
    float* out = (float*)d_out;

    int xs = in_sizes[0] / (BB * NCOL);
    if (xs < 1) xs = 1;

    cudaFuncSetAttribute(k_rel, cudaFuncAttributeMaxDynamicSharedMemorySize, 128 * 1024);

    k_wct<<<256, 512>>>(w_e);
    k_tbuild<<<1000, 128>>>();
    k_gather<<<BB, 256>>>(x, xs, e_emb, r_emb, d_frq, d_phi, d_amp,
                          m_frq, m_phi, m_amp, w_rp);
    k_gemm_mma<<<dim3(2, 128), 256>>>(e_emb, x, xs);
    k_rel<<<TSLICE * RB, 512, 128 * 1024>>>();
    k_comb<<<BB, 128>>>(out);
}